// round 6
// baseline (speedup 1.0000x reference)
#include <cuda_runtime.h>
#include <cstdio>
#include <math.h>

#define BB 128
#define TT 512
#define DD 100
#define HH 100
#define G4 400
#define LL 25

typedef unsigned long long ull;

// ---------------- device scratch (static; no runtime allocation) ----------------
// gin stored REMAPPED: index = k*4 + gtype  (k=0..99, gtype 0:i 1:f 2:g 3:o)
__device__ float g_gin[2][TT][BB][G4];
__device__ float g_h[2][TT][BB][HH];            // hidden states, both dirs
__device__ float g_em[(size_t)BB * TT * LL];    // emissions [b][t][l]
__device__ float g_res[BB];                     // per-batch logZ - gold
__device__ ull   g_ts[8];                       // [k0_start,k0_end,k1_start,...] timing

// ---------------- helpers ----------------
__device__ __forceinline__ ull gtimer() {
    ull t; asm volatile("mov.u64 %0, %%globaltimer;" : "=l"(t)); return t;
}
__device__ __forceinline__ void t_begin(int id) {
    if (threadIdx.x == 0) atomicMin(&g_ts[2 * id], gtimer());
}
__device__ __forceinline__ void t_end(int id) {
    if (threadIdx.x == 0) atomicMax(&g_ts[2 * id + 1], gtimer());
}
__device__ __forceinline__ float htanh(float x) {
    float y; asm("tanh.approx.f32 %0, %1;" : "=f"(y) : "f"(x)); return y;
}
__device__ __forceinline__ float hsig(float x) {
    return fmaf(0.5f, htanh(0.5f * x), 0.5f);
}
__device__ __forceinline__ ull ffma2(ull a, ull b, ull c) {
    ull d;
    asm("fma.rn.f32x2 %0, %1, %2, %3;" : "=l"(d) : "l"(a), "l"(b), "l"(c));
    return d;
}
__device__ __forceinline__ float2 u2f(ull u) {
    float2 f;
    asm("mov.b64 {%0, %1}, %2;" : "=f"(f.x), "=f"(f.y) : "l"(u));
    return f;
}

// ================= Kernel 0: timer init =================
__global__ void k_tinit() {
    if (threadIdx.x < 4) { g_ts[2 * threadIdx.x] = ~0ull; g_ts[2 * threadIdx.x + 1] = 0ull; }
}

// ================= Kernel 1: embedding lookup + input projection GEMM =================
// 128-row x 64-col tiles, 128 threads, thread tile 8x8, f32x2 k-pair packing.
#define XS_STRIDE 102
#define PROJ_SMEM ((128 * XS_STRIDE + 64 * XS_STRIDE) * 4)

__global__ void __launch_bounds__(128) k_input_proj(
    const int* __restrict__ tok, const float* __restrict__ emb,
    const float* __restrict__ wih_f, const float* __restrict__ wih_b,
    const float* __restrict__ bih_f, const float* __restrict__ bhh_f,
    const float* __restrict__ bih_b, const float* __restrict__ bhh_b)
{
    t_begin(0);
    extern __shared__ float psm[];
    float* xs = psm;                    // [128][102]
    float* wc = psm + 128 * XS_STRIDE;  // [64][102]
    const int m0 = blockIdx.x * 128;
    const int c0 = blockIdx.y * 64;
    const int tid = threadIdx.x;

    // stage x tile (gathered embeddings): thread <-> row
    {
        const int r = tid;
        const int m = m0 + r;
        const int t = m >> 7, b = m & 127;
        const int token = tok[b * TT + t];
        const float4* src = (const float4*)(emb + (size_t)token * DD);
        float* dst = xs + r * XS_STRIDE;
        #pragma unroll
        for (int q = 0; q < 25; ++q) {
            float4 v = src[q];
            *(float2*)(dst + 4 * q)     = make_float2(v.x, v.y);
            *(float2*)(dst + 4 * q + 2) = make_float2(v.z, v.w);
        }
    }
    for (int i = tid; i < 64 * 25; i += 128) {
        const int cc = i / 25, q = i - cc * 25;
        const int col = c0 + cc;
        float4 v = make_float4(0.f, 0.f, 0.f, 0.f);
        if (col < 400)      v = *(const float4*)(wih_f + col * DD + 4 * q);
        else if (col < 800) v = *(const float4*)(wih_b + (col - 400) * DD + 4 * q);
        float* dst = wc + cc * XS_STRIDE + 4 * q;
        *(float2*)(dst)     = make_float2(v.x, v.y);
        *(float2*)(dst + 2) = make_float2(v.z, v.w);
    }
    __syncthreads();

    const int ct = tid >> 4;   // 0..7
    const int rt = tid & 15;   // rows rt + 16*i

    ull acc[8][4][2];
    #pragma unroll
    for (int i = 0; i < 8; ++i)
        #pragma unroll
        for (int j = 0; j < 4; ++j) { acc[i][j][0] = 0ull; acc[i][j][1] = 0ull; }

    #pragma unroll 2
    for (int kp = 0; kp < 50; ++kp) {
        ull xv[8];
        #pragma unroll
        for (int i = 0; i < 8; ++i)
            xv[i] = *(const ull*)(xs + (rt + 16 * i) * XS_STRIDE + 2 * kp);
        ull wv[4][2];
        #pragma unroll
        for (int j = 0; j < 4; ++j) {
            #pragma unroll
            for (int e = 0; e < 2; ++e)
                wv[j][e] = *(const ull*)(wc + (2 * ct + 16 * j + e) * XS_STRIDE + 2 * kp);
        }
        #pragma unroll
        for (int i = 0; i < 8; ++i)
            #pragma unroll
            for (int j = 0; j < 4; ++j) {
                acc[i][j][0] = ffma2(xv[i], wv[j][0], acc[i][j][0]);
                acc[i][j][1] = ffma2(xv[i], wv[j][1], acc[i][j][1]);
            }
    }

    // store with gate remap: g in [0,400) per dir -> idx = (g%100)*4 + g/100
    #pragma unroll
    for (int i = 0; i < 8; ++i) {
        const int r = rt + 16 * i;
        const int m = m0 + r;
        const int t = m >> 7, b = m & 127;
        #pragma unroll
        for (int j = 0; j < 4; ++j) {
            const int col = c0 + 2 * ct + 16 * j;
            if (col < 800) {
                float2 s0 = u2f(acc[i][j][0]);
                float2 s1 = u2f(acc[i][j][1]);
                float r0 = s0.x + s0.y;
                float r1 = s1.x + s1.y;
                #pragma unroll
                for (int e = 0; e < 2; ++e) {
                    const int c = col + e;
                    float v = e ? r1 : r0;
                    if (c < 400) {
                        v += bih_f[c] + bhh_f[c];
                        g_gin[0][t][b][(c % 100) * 4 + c / 100] = v;
                    } else {
                        const int c2 = c - 400;
                        v += bih_b[c2] + bhh_b[c2];
                        g_gin[1][t][b][(c2 % 100) * 4 + c2 / 100] = v;
                    }
                }
            }
        }
    }
    t_end(0);
}

// ================= Kernel 2: LSTM recurrence — shuffle exchange, 1 barrier/step =================
// tid -> (k = tid>>2, gt = tid&3); gate row = gt*100+k. 4 gates of unit k in
// adjacent lanes; exchange activations via 2-round butterfly, c/h computed
// redundantly in all 4 lanes (bitwise identical).
__global__ void __launch_bounds__(400, 1) k_lstm(
    const float* __restrict__ whh_f, const float* __restrict__ whh_b)
{
    t_begin(1);
    __shared__ __align__(16) float hsm[208];  // [p][ h0(2) h1(2) ]

    const int dir = blockIdx.y;
    const int b0  = blockIdx.x * 2;
    const int tid = threadIdx.x;
    const int k   = tid >> 2;
    const int gt  = tid & 3;
    const float* whh = (dir ? whh_b : whh_f) + (gt * 100 + k) * 100;

    ull w[50];
    #pragma unroll
    for (int q = 0; q < 50; ++q) w[q] = *(const ull*)(whh + 2 * q);

    if (tid < 52) *(float4*)(hsm + 4 * tid) = make_float4(0.f, 0.f, 0.f, 0.f);
    float c0 = 0.f, c1 = 0.f;
    __syncthreads();

    int t = dir ? (TT - 1) : 0;
    const int tstep = dir ? -1 : 1;
    float pre0 = g_gin[dir][t][b0][tid];
    float pre1 = g_gin[dir][t][b0 + 1][tid];
    const unsigned FULL = 0xffffffffu;

    for (int s = 0; s < TT; ++s, t += tstep) {
        int tn = t + tstep;
        tn = (tn < 0) ? 0 : ((tn > TT - 1) ? TT - 1 : tn);
        float nx0 = g_gin[dir][tn][b0][tid];
        float nx1 = g_gin[dir][tn][b0 + 1][tid];

        ull a0a = 0ull, a0b = 0ull, a1a = 0ull, a1b = 0ull;
        #pragma unroll
        for (int q = 0; q < 50; q += 2) {
            ulonglong2 ha = *(const ulonglong2*)(hsm + 4 * q);
            ulonglong2 hb = *(const ulonglong2*)(hsm + 4 * q + 4);
            a0a = ffma2(w[q],     ha.x, a0a);
            a1a = ffma2(w[q],     ha.y, a1a);
            a0b = ffma2(w[q + 1], hb.x, a0b);
            a1b = ffma2(w[q + 1], hb.y, a1b);
        }
        float2 p0a = u2f(a0a), p0b = u2f(a0b), p1a = u2f(a1a), p1b = u2f(a1b);
        float acc0 = pre0 + (p0a.x + p0a.y) + (p0b.x + p0b.y);
        float acc1 = pre1 + (p1a.x + p1a.y) + (p1b.x + p1b.y);

        float v0, v1;
        if (gt == 2) { v0 = htanh(acc0); v1 = htanh(acc1); }
        else         { v0 = hsig(acc0);  v1 = hsig(acc1); }

        // butterfly exchange within the 4-lane group
        float x0 = __shfl_xor_sync(FULL, v0, 1);
        float x1 = __shfl_xor_sync(FULL, v1, 1);
        float pa0 = (gt & 1) ? x0 : v0;   // gate (gt&~1)
        float pb0 = (gt & 1) ? v0 : x0;   // gate (gt|1)
        float pa1 = (gt & 1) ? x1 : v1;
        float pb1 = (gt & 1) ? v1 : x1;
        float qa0 = __shfl_xor_sync(FULL, pa0, 2);
        float qb0 = __shfl_xor_sync(FULL, pb0, 2);
        float qa1 = __shfl_xor_sync(FULL, pa1, 2);
        float qb1 = __shfl_xor_sync(FULL, pb1, 2);
        const bool lo = (gt < 2);
        float iv0 = lo ? pa0 : qa0, fv0 = lo ? pb0 : qb0;
        float gv0 = lo ? qa0 : pa0, ov0 = lo ? qb0 : pb0;
        float iv1 = lo ? pa1 : qa1, fv1 = lo ? pb1 : qb1;
        float gv1 = lo ? qa1 : pa1, ov1 = lo ? qb1 : pb1;

        c0 = fv0 * c0 + iv0 * gv0;
        float h0 = ov0 * htanh(c0);
        c1 = fv1 * c1 + iv1 * gv1;
        float h1 = ov1 * htanh(c1);

        if (gt == 0) {
            hsm[4 * (k >> 1) + (k & 1)] = h0;
            g_h[dir][t][b0][k] = h0;
        } else if (gt == 1) {
            hsm[4 * (k >> 1) + 2 + (k & 1)] = h1;
            g_h[dir][t][b0 + 1][k] = h1;
        }
        pre0 = nx0; pre1 = nx1;
        __syncthreads();
    }
    t_end(1);
}

// ================= Kernel 3: emissions = [h_f|h_b] . w_tag^T + b_tag =================
#define HS_STRIDE 202
#define EMIT_SMEM ((128 * HS_STRIDE + 25 * HS_STRIDE) * 4)

__global__ void __launch_bounds__(320) k_emit(
    const float* __restrict__ wtag, const float* __restrict__ btag)
{
    t_begin(2);
    extern __shared__ float esm[];
    float* hs = esm;                    // [128][202]
    float* wt = esm + 128 * HS_STRIDE;  // [25][202]
    const int tid = threadIdx.x;
    const int m0 = blockIdx.x * 128;

    for (int i = tid; i < 25 * 100; i += 320) {
        const int l = i / 100, kp = i - l * 100;
        *(float2*)(wt + l * HS_STRIDE + 2 * kp) = *(const float2*)(wtag + l * 200 + 2 * kp);
    }
    for (int i = tid; i < 128 * 100; i += 320) {
        const int r = i / 100, kp = i - r * 100;
        const int m = m0 + r;
        const int t = m >> 7, b = m & 127;
        const int kk = 2 * kp;
        float2 v = (kk < 100) ? *(const float2*)(&g_h[0][t][b][kk])
                              : *(const float2*)(&g_h[1][t][b][kk - 100]);
        *(float2*)(hs + r * HS_STRIDE + kk) = v;
    }
    __syncthreads();

    const int rp = tid / 5;
    const int lg = tid - rp * 5;
    ull acc[2][5];
    #pragma unroll
    for (int rr = 0; rr < 2; ++rr)
        #pragma unroll
        for (int j = 0; j < 5; ++j) acc[rr][j] = 0ull;

    const float* h0p = hs + (2 * rp) * HS_STRIDE;
    const float* h1p = hs + (2 * rp + 1) * HS_STRIDE;
    #pragma unroll 4
    for (int kp = 0; kp < 100; ++kp) {
        ull hv0 = *(const ull*)(h0p + 2 * kp);
        ull hv1 = *(const ull*)(h1p + 2 * kp);
        #pragma unroll
        for (int j = 0; j < 5; ++j) {
            ull wv = *(const ull*)(wt + (5 * lg + j) * HS_STRIDE + 2 * kp);
            acc[0][j] = ffma2(hv0, wv, acc[0][j]);
            acc[1][j] = ffma2(hv1, wv, acc[1][j]);
        }
    }
    #pragma unroll
    for (int rr = 0; rr < 2; ++rr) {
        const int r = 2 * rp + rr;
        const int m = m0 + r;
        const int t = m >> 7, b = m & 127;
        #pragma unroll
        for (int j = 0; j < 5; ++j) {
            const int l = 5 * lg + j;
            float2 p = u2f(acc[rr][j]);
            g_em[((size_t)b * TT + t) * LL + l] = p.x + p.y + btag[l];
        }
    }
    t_end(2);
}

// ================= Kernel 4: CRF NLL (scaled-prob forward, depth-7 chains) =================
__global__ void __launch_bounds__(32) k_crf(
    const float* __restrict__ trans, const float* __restrict__ strans,
    const float* __restrict__ etrans, const int* __restrict__ tags,
    const int* __restrict__ lengths)
{
    t_begin(3);
    __shared__ float E[640];
    __shared__ float tr[640];
    __shared__ float As[32];
    const int b = blockIdx.x;
    const int lane = threadIdx.x;

    for (int i = lane; i < 625; i += 32) {
        float v = trans[i];
        tr[i] = v;
        E[i] = __expf(v);
    }
    __syncwarp();

    const int len = lengths[b];
    const int* tg = tags + b * TT;
    const float* em = g_em + (size_t)b * TT * LL;

    float gp = 0.f;
    for (int t = 1 + lane; t < TT; t += 32) {
        if (t < len) {
            int tp = tg[t - 1], tc = tg[t];
            gp += tr[tp * 25 + tc] + em[t * LL + tc];
        }
    }
    #pragma unroll
    for (int off = 16; off; off >>= 1) gp += __shfl_down_sync(0xffffffffu, gp, off);
    float gold = __shfl_sync(0xffffffffu, gp, 0);
    if (lane == 0) {
        int t0 = tg[0];
        gold += strans[t0] + em[t0];
        gold += etrans[tg[len - 1]];
    }
    gold = __shfl_sync(0xffffffffu, gold, 0);

    float A = 0.f, off = 0.f;
    if (lane < LL) A = __expf(strans[lane] + em[lane]);
    As[lane] = A;
    __syncwarp();

    float emn = (lane < LL) ? em[LL + lane] : 0.f;
    for (int t = 1; t < TT; ++t) {
        const float emc = emn;
        const int t2 = (t + 1 < TT) ? (t + 1) : t;
        emn = (lane < LL) ? em[t2 * LL + lane] : 0.f;

        if (t < len) {
            float s0 = 0.f, s1 = 0.f, s2 = 0.f, s3 = 0.f;
            #pragma unroll
            for (int p = 0; p < 24; p += 4) {
                s0 = fmaf(As[p],     E[p * 25 + lane],       s0);
                s1 = fmaf(As[p + 1], E[(p + 1) * 25 + lane], s1);
                s2 = fmaf(As[p + 2], E[(p + 2) * 25 + lane], s2);
                s3 = fmaf(As[p + 3], E[(p + 3) * 25 + lane], s3);
            }
            s0 = fmaf(As[24], E[24 * 25 + lane], s0);
            A = ((s0 + s1) + (s2 + s3)) * __expf(emc);
        }
        if ((t & 15) == 15) {
            float m = A;
            #pragma unroll
            for (int o = 16; o; o >>= 1) m = fmaxf(m, __shfl_xor_sync(0xffffffffu, m, o));
            off += __logf(m);
            A = __fdividef(A, m);
        }
        __syncwarp();
        As[lane] = A;
        __syncwarp();
    }

    float val = (lane < LL) ? A * __expf(etrans[lane]) : 0.f;
    #pragma unroll
    for (int o = 16; o; o >>= 1) val += __shfl_xor_sync(0xffffffffu, val, o);
    float logZ = off + __logf(val);
    if (lane == 0) g_res[b] = logZ - gold;
    t_end(3);
}

// ================= Kernel 5: final reduction + timing report =================
__global__ void __launch_bounds__(128) k_reduce(float* __restrict__ out)
{
    __shared__ float s[128];
    s[threadIdx.x] = g_res[threadIdx.x];
    __syncthreads();
    for (int st = 64; st > 0; st >>= 1) {
        if (threadIdx.x < st) s[threadIdx.x] += s[threadIdx.x + st];
        __syncthreads();
    }
    if (threadIdx.x == 0) {
        out[0] = s[0];
        printf("KT proj=%llu lstm=%llu emit=%llu crf=%llu ns\n",
               g_ts[1] - g_ts[0], g_ts[3] - g_ts[2],
               g_ts[5] - g_ts[4], g_ts[7] - g_ts[6]);
    }
}

// ================= launch =================
extern "C" void kernel_launch(void* const* d_in, const int* in_sizes, int n_in,
                              void* d_out, int out_size)
{
    const int*   tok     = (const int*)  d_in[0];
    const int*   tag     = (const int*)  d_in[1];
    const int*   lengths = (const int*)  d_in[2];
    const float* emb     = (const float*)d_in[3];
    const float* wih_f   = (const float*)d_in[4];
    const float* whh_f   = (const float*)d_in[5];
    const float* bih_f   = (const float*)d_in[6];
    const float* bhh_f   = (const float*)d_in[7];
    const float* wih_b   = (const float*)d_in[8];
    const float* whh_b   = (const float*)d_in[9];
    const float* bih_b   = (const float*)d_in[10];
    const float* bhh_b   = (const float*)d_in[11];
    const float* wtag    = (const float*)d_in[12];
    const float* btag    = (const float*)d_in[13];
    const float* trans   = (const float*)d_in[14];
    const float* strans  = (const float*)d_in[15];
    const float* etrans  = (const float*)d_in[16];
    float* out = (float*)d_out;

    cudaFuncSetAttribute(k_input_proj, cudaFuncAttributeMaxDynamicSharedMemorySize, PROJ_SMEM);
    cudaFuncSetAttribute(k_emit, cudaFuncAttributeMaxDynamicSharedMemorySize, EMIT_SMEM);

    k_tinit<<<1, 32>>>();
    k_input_proj<<<dim3(512, 13), 128, PROJ_SMEM>>>(tok, emb, wih_f, wih_b,
                                                    bih_f, bhh_f, bih_b, bhh_b);
    k_lstm<<<dim3(64, 2), 400>>>(whh_f, whh_b);
    k_emit<<<512, 320, EMIT_SMEM>>>(wtag, btag);
    k_crf<<<128, 32>>>(trans, strans, etrans, tag, lengths);
    k_reduce<<<1, 128>>>(out);
}

// round 7
// speedup vs baseline: 1.7559x; 1.7559x over previous
#include <cuda_runtime.h>
#include <math.h>

#define BB 128
#define TT 512
#define DD 100
#define HH 100
#define G4 400
#define LL 25

typedef unsigned long long ull;

// ---------------- device scratch (static; no runtime allocation) ----------------
__device__ float g_gin[2][TT][BB][G4];          // input projection + biases
__device__ float g_h[2][TT][BB][HH];            // hidden states, both dirs
__device__ float g_em[(size_t)BB * TT * LL];    // emissions [b][t][l]
__device__ float g_res[BB];                     // per-batch logZ - gold

// ---------------- helpers ----------------
__device__ __forceinline__ float htanh(float x) {
    float y; asm("tanh.approx.f32 %0, %1;" : "=f"(y) : "f"(x)); return y;
}
__device__ __forceinline__ float hsig(float x) {
    return fmaf(0.5f, htanh(0.5f * x), 0.5f);
}
__device__ __forceinline__ ull ffma2(ull a, ull b, ull c) {
    ull d;
    asm("fma.rn.f32x2 %0, %1, %2, %3;" : "=l"(d) : "l"(a), "l"(b), "l"(c));
    return d;
}
__device__ __forceinline__ float2 u2f(ull u) {
    float2 f;
    asm("mov.b64 {%0, %1}, %2;" : "=f"(f.x), "=f"(f.y) : "l"(u));
    return f;
}

// ================= dummy launches (shift ncu capture window onto k_lstm) =================
__global__ void k_nop() {}

// ================= Kernel 1: embedding lookup + input projection GEMM =================
// 128-row x 64-col tiles, 128 threads, thread tile 8x8, f32x2 k-pair packing.
#define XS_STRIDE 102
#define PROJ_SMEM ((128 * XS_STRIDE + 64 * XS_STRIDE) * 4)

__global__ void __launch_bounds__(128) k_input_proj(
    const int* __restrict__ tok, const float* __restrict__ emb,
    const float* __restrict__ wih_f, const float* __restrict__ wih_b,
    const float* __restrict__ bih_f, const float* __restrict__ bhh_f,
    const float* __restrict__ bih_b, const float* __restrict__ bhh_b)
{
    extern __shared__ float psm[];
    float* xs = psm;                    // [128][102]
    float* wc = psm + 128 * XS_STRIDE;  // [64][102]
    const int m0 = blockIdx.x * 128;
    const int c0 = blockIdx.y * 64;
    const int tid = threadIdx.x;

    {
        const int r = tid;
        const int m = m0 + r;
        const int t = m >> 7, b = m & 127;
        const int token = tok[b * TT + t];
        const float4* src = (const float4*)(emb + (size_t)token * DD);
        float* dst = xs + r * XS_STRIDE;
        #pragma unroll
        for (int q = 0; q < 25; ++q) {
            float4 v = src[q];
            *(float2*)(dst + 4 * q)     = make_float2(v.x, v.y);
            *(float2*)(dst + 4 * q + 2) = make_float2(v.z, v.w);
        }
    }
    for (int i = tid; i < 64 * 25; i += 128) {
        const int cc = i / 25, q = i - cc * 25;
        const int col = c0 + cc;
        float4 v = make_float4(0.f, 0.f, 0.f, 0.f);
        if (col < 400)      v = *(const float4*)(wih_f + col * DD + 4 * q);
        else if (col < 800) v = *(const float4*)(wih_b + (col - 400) * DD + 4 * q);
        float* dst = wc + cc * XS_STRIDE + 4 * q;
        *(float2*)(dst)     = make_float2(v.x, v.y);
        *(float2*)(dst + 2) = make_float2(v.z, v.w);
    }
    __syncthreads();

    const int ct = tid >> 4;   // 0..7
    const int rt = tid & 15;   // rows rt + 16*i

    ull acc[8][4][2];
    #pragma unroll
    for (int i = 0; i < 8; ++i)
        #pragma unroll
        for (int j = 0; j < 4; ++j) { acc[i][j][0] = 0ull; acc[i][j][1] = 0ull; }

    #pragma unroll 2
    for (int kp = 0; kp < 50; ++kp) {
        ull xv[8];
        #pragma unroll
        for (int i = 0; i < 8; ++i)
            xv[i] = *(const ull*)(xs + (rt + 16 * i) * XS_STRIDE + 2 * kp);
        ull wv[4][2];
        #pragma unroll
        for (int j = 0; j < 4; ++j) {
            #pragma unroll
            for (int e = 0; e < 2; ++e)
                wv[j][e] = *(const ull*)(wc + (2 * ct + 16 * j + e) * XS_STRIDE + 2 * kp);
        }
        #pragma unroll
        for (int i = 0; i < 8; ++i)
            #pragma unroll
            for (int j = 0; j < 4; ++j) {
                acc[i][j][0] = ffma2(xv[i], wv[j][0], acc[i][j][0]);
                acc[i][j][1] = ffma2(xv[i], wv[j][1], acc[i][j][1]);
            }
    }

    #pragma unroll
    for (int i = 0; i < 8; ++i) {
        const int r = rt + 16 * i;
        const int m = m0 + r;
        const int t = m >> 7, b = m & 127;
        #pragma unroll
        for (int j = 0; j < 4; ++j) {
            const int col = c0 + 2 * ct + 16 * j;
            if (col < 800) {
                float2 s0 = u2f(acc[i][j][0]);
                float2 s1 = u2f(acc[i][j][1]);
                float r0 = s0.x + s0.y;
                float r1 = s1.x + s1.y;
                if (col < 400) {
                    r0 += bih_f[col] + bhh_f[col];
                    r1 += bih_f[col + 1] + bhh_f[col + 1];
                    *(float2*)(&g_gin[0][t][b][col]) = make_float2(r0, r1);
                } else {
                    const int c2 = col - 400;
                    r0 += bih_b[c2] + bhh_b[c2];
                    r1 += bih_b[c2 + 1] + bhh_b[c2 + 1];
                    *(float2*)(&g_gin[1][t][b][c2]) = make_float2(r0, r1);
                }
            }
        }
    }
}

// ================= Kernel 2: LSTM recurrence (W_hh in registers, HW tanh) =================
__global__ void __launch_bounds__(400, 1) k_lstm(
    const float* __restrict__ whh_f, const float* __restrict__ whh_b)
{
    __shared__ __align__(16) float hsm[208];  // interleaved: [p][ h0(2) h1(2) ]
    __shared__ float gbuf[800];

    const int dir = blockIdx.y;
    const int b0  = blockIdx.x * 2;
    const int g   = threadIdx.x;              // gate 0..399
    const float* whh = (dir ? whh_b : whh_f) + g * 100;

    ull w[50];
    #pragma unroll
    for (int q = 0; q < 50; ++q) w[q] = *(const ull*)(whh + 2 * q);

    if (g < 52) *(float4*)(hsm + 4 * g) = make_float4(0.f, 0.f, 0.f, 0.f);
    float cv = 0.f;
    __syncthreads();

    const int gtype = g / 100;
    int t = dir ? (TT - 1) : 0;
    const int tstep = dir ? -1 : 1;
    float pre0 = g_gin[dir][t][b0][g];
    float pre1 = g_gin[dir][t][b0 + 1][g];

    const int pe = (g >= 100 && g < 200) ? 1 : 0;
    const int pk = g - 100 * pe;

    for (int s = 0; s < TT; ++s, t += tstep) {
        int tn = t + tstep;
        tn = (tn < 0) ? 0 : ((tn > TT - 1) ? TT - 1 : tn);
        float nx0 = g_gin[dir][tn][b0][g];
        float nx1 = g_gin[dir][tn][b0 + 1][g];

        ull a0a = 0ull, a0b = 0ull, a1a = 0ull, a1b = 0ull;
        #pragma unroll
        for (int q = 0; q < 50; q += 2) {
            ulonglong2 ha = *(const ulonglong2*)(hsm + 4 * q);
            ulonglong2 hb = *(const ulonglong2*)(hsm + 4 * q + 4);
            a0a = ffma2(w[q],     ha.x, a0a);
            a1a = ffma2(w[q],     ha.y, a1a);
            a0b = ffma2(w[q + 1], hb.x, a0b);
            a1b = ffma2(w[q + 1], hb.y, a1b);
        }
        float2 p0a = u2f(a0a), p0b = u2f(a0b), p1a = u2f(a1a), p1b = u2f(a1b);
        float acc0 = pre0 + (p0a.x + p0a.y) + (p0b.x + p0b.y);
        float acc1 = pre1 + (p1a.x + p1a.y) + (p1b.x + p1b.y);

        float v0, v1;
        if (gtype == 2) { v0 = htanh(acc0); v1 = htanh(acc1); }
        else            { v0 = hsig(acc0);  v1 = hsig(acc1); }
        gbuf[g]       = v0;
        gbuf[400 + g] = v1;
        __syncthreads();

        if (g < 200) {
            const int base = 400 * pe;
            float iv = gbuf[base + pk],       fv = gbuf[base + pk + 100];
            float gv = gbuf[base + pk + 200], ov = gbuf[base + pk + 300];
            cv = fv * cv + iv * gv;
            float hv = ov * htanh(cv);
            hsm[4 * (pk >> 1) + 2 * pe + (pk & 1)] = hv;
            g_h[dir][t][b0 + pe][pk] = hv;
        }
        pre0 = nx0; pre1 = nx1;
        __syncthreads();
    }
}

// ================= Kernel 3: emissions — 64-row tiles for 3 blocks/SM =================
#define HS_STRIDE 202
#define EMIT_SMEM ((64 * HS_STRIDE + 25 * HS_STRIDE) * 4)

__global__ void __launch_bounds__(320) k_emit(
    const float* __restrict__ wtag, const float* __restrict__ btag)
{
    extern __shared__ float esm[];
    float* hs = esm;                   // [64][202]
    float* wt = esm + 64 * HS_STRIDE;  // [25][202]
    const int tid = threadIdx.x;
    const int m0 = blockIdx.x * 64;

    for (int i = tid; i < 25 * 100; i += 320) {
        const int l = i / 100, kp = i - l * 100;
        *(float2*)(wt + l * HS_STRIDE + 2 * kp) = *(const float2*)(wtag + l * 200 + 2 * kp);
    }
    for (int i = tid; i < 64 * 100; i += 320) {
        const int r = i / 100, kp = i - r * 100;
        const int m = m0 + r;
        const int t = m >> 7, b = m & 127;
        const int kk = 2 * kp;
        float2 v = (kk < 100) ? *(const float2*)(&g_h[0][t][b][kk])
                              : *(const float2*)(&g_h[1][t][b][kk - 100]);
        *(float2*)(hs + r * HS_STRIDE + kk) = v;
    }
    __syncthreads();

    const int r  = tid / 5;       // 0..63
    const int lg = tid - r * 5;   // labels {5lg..5lg+4}
    ull acc[5];
    #pragma unroll
    for (int j = 0; j < 5; ++j) acc[j] = 0ull;

    const float* hp = hs + r * HS_STRIDE;
    #pragma unroll 4
    for (int kp = 0; kp < 100; ++kp) {
        ull hv = *(const ull*)(hp + 2 * kp);
        #pragma unroll
        for (int j = 0; j < 5; ++j) {
            ull wv = *(const ull*)(wt + (5 * lg + j) * HS_STRIDE + 2 * kp);
            acc[j] = ffma2(hv, wv, acc[j]);
        }
    }
    {
        const int m = m0 + r;
        const int t = m >> 7, b = m & 127;
        #pragma unroll
        for (int j = 0; j < 5; ++j) {
            const int l = 5 * lg + j;
            float2 p = u2f(acc[j]);
            g_em[((size_t)b * TT + t) * LL + l] = p.x + p.y + btag[l];
        }
    }
}

// ================= Kernel 4: CRF NLL (scaled-prob forward, depth-7 chains) =================
__global__ void __launch_bounds__(32) k_crf(
    const float* __restrict__ trans, const float* __restrict__ strans,
    const float* __restrict__ etrans, const int* __restrict__ tags,
    const int* __restrict__ lengths)
{
    __shared__ float E[640];
    __shared__ float tr[640];
    __shared__ float As[32];
    const int b = blockIdx.x;
    const int lane = threadIdx.x;

    for (int i = lane; i < 625; i += 32) {
        float v = trans[i];
        tr[i] = v;
        E[i] = __expf(v);
    }
    __syncwarp();

    const int len = lengths[b];
    const int* tg = tags + b * TT;
    const float* em = g_em + (size_t)b * TT * LL;

    float gp = 0.f;
    for (int t = 1 + lane; t < TT; t += 32) {
        if (t < len) {
            int tp = tg[t - 1], tc = tg[t];
            gp += tr[tp * 25 + tc] + em[t * LL + tc];
        }
    }
    #pragma unroll
    for (int off = 16; off; off >>= 1) gp += __shfl_down_sync(0xffffffffu, gp, off);
    float gold = __shfl_sync(0xffffffffu, gp, 0);
    if (lane == 0) {
        int t0 = tg[0];
        gold += strans[t0] + em[t0];
        gold += etrans[tg[len - 1]];
    }
    gold = __shfl_sync(0xffffffffu, gold, 0);

    float A = 0.f, off = 0.f;
    if (lane < LL) A = __expf(strans[lane] + em[lane]);
    As[lane] = A;
    __syncwarp();

    float emn = (lane < LL) ? em[LL + lane] : 0.f;
    for (int t = 1; t < TT; ++t) {
        const float emc = emn;
        const int t2 = (t + 1 < TT) ? (t + 1) : t;
        emn = (lane < LL) ? em[t2 * LL + lane] : 0.f;

        if (t < len) {
            float s0 = 0.f, s1 = 0.f, s2 = 0.f, s3 = 0.f;
            #pragma unroll
            for (int p = 0; p < 24; p += 4) {
                s0 = fmaf(As[p],     E[p * 25 + lane],       s0);
                s1 = fmaf(As[p + 1], E[(p + 1) * 25 + lane], s1);
                s2 = fmaf(As[p + 2], E[(p + 2) * 25 + lane], s2);
                s3 = fmaf(As[p + 3], E[(p + 3) * 25 + lane], s3);
            }
            s0 = fmaf(As[24], E[24 * 25 + lane], s0);
            A = ((s0 + s1) + (s2 + s3)) * __expf(emc);
        }
        if ((t & 15) == 15) {
            float m = A;
            #pragma unroll
            for (int o = 16; o; o >>= 1) m = fmaxf(m, __shfl_xor_sync(0xffffffffu, m, o));
            off += __logf(m);
            A = __fdividef(A, m);
        }
        __syncwarp();
        As[lane] = A;
        __syncwarp();
    }

    float val = (lane < LL) ? A * __expf(etrans[lane]) : 0.f;
    #pragma unroll
    for (int o = 16; o; o >>= 1) val += __shfl_xor_sync(0xffffffffu, val, o);
    float logZ = off + __logf(val);
    if (lane == 0) g_res[b] = logZ - gold;
}

// ================= Kernel 5: final fixed-order reduction =================
__global__ void __launch_bounds__(128) k_reduce(float* __restrict__ out)
{
    __shared__ float s[128];
    s[threadIdx.x] = g_res[threadIdx.x];
    __syncthreads();
    for (int st = 64; st > 0; st >>= 1) {
        if (threadIdx.x < st) s[threadIdx.x] += s[threadIdx.x + st];
        __syncthreads();
    }
    if (threadIdx.x == 0) out[0] = s[0];
}

// ================= launch =================
extern "C" void kernel_launch(void* const* d_in, const int* in_sizes, int n_in,
                              void* d_out, int out_size)
{
    const int*   tok     = (const int*)  d_in[0];
    const int*   tag     = (const int*)  d_in[1];
    const int*   lengths = (const int*)  d_in[2];
    const float* emb     = (const float*)d_in[3];
    const float* wih_f   = (const float*)d_in[4];
    const float* whh_f   = (const float*)d_in[5];
    const float* bih_f   = (const float*)d_in[6];
    const float* bhh_f   = (const float*)d_in[7];
    const float* wih_b   = (const float*)d_in[8];
    const float* whh_b   = (const float*)d_in[9];
    const float* bih_b   = (const float*)d_in[10];
    const float* bhh_b   = (const float*)d_in[11];
    const float* wtag    = (const float*)d_in[12];
    const float* btag    = (const float*)d_in[13];
    const float* trans   = (const float*)d_in[14];
    const float* strans  = (const float*)d_in[15];
    const float* etrans  = (const float*)d_in[16];
    float* out = (float*)d_out;

    cudaFuncSetAttribute(k_input_proj, cudaFuncAttributeMaxDynamicSharedMemorySize, PROJ_SMEM);
    cudaFuncSetAttribute(k_emit, cudaFuncAttributeMaxDynamicSharedMemorySize, EMIT_SMEM);

    // two no-op launches shift the ncu capture window (4th launch) onto k_lstm
    k_nop<<<1, 32>>>();
    k_nop<<<1, 32>>>();
    k_input_proj<<<dim3(512, 13), 128, PROJ_SMEM>>>(tok, emb, wih_f, wih_b,
                                                    bih_f, bhh_f, bih_b, bhh_b);
    k_lstm<<<dim3(64, 2), 400>>>(whh_f, whh_b);
    k_emit<<<1024, 320, EMIT_SMEM>>>(wtag, btag);
    k_crf<<<128, 32>>>(trans, strans, etrans, tag, lengths);
    k_reduce<<<1, 128>>>(out);
}

// round 8
// speedup vs baseline: 1.7871x; 1.0177x over previous
#include <cuda_runtime.h>
#include <math.h>

#define BB 128
#define TT 512
#define DD 100
#define HH 100
#define G4 400
#define LL 25

typedef unsigned long long ull;

// ---------------- device scratch (static; no runtime allocation) ----------------
__device__ float g_gin[2][TT][BB][G4];          // input projection + biases
__device__ float g_h[2][TT][BB][HH];            // hidden states, both dirs
__device__ float g_em[(size_t)BB * TT * LL];    // emissions [b][t][l]
__device__ float g_res[BB];                     // per-batch logZ - gold

// ---------------- helpers ----------------
__device__ __forceinline__ float htanh(float x) {
    float y; asm("tanh.approx.f32 %0, %1;" : "=f"(y) : "f"(x)); return y;
}
__device__ __forceinline__ float hsig(float x) {
    return fmaf(0.5f, htanh(0.5f * x), 0.5f);
}
__device__ __forceinline__ ull ffma2(ull a, ull b, ull c) {
    ull d;
    asm("fma.rn.f32x2 %0, %1, %2, %3;" : "=l"(d) : "l"(a), "l"(b), "l"(c));
    return d;
}
__device__ __forceinline__ float2 u2f(ull u) {
    float2 f;
    asm("mov.b64 {%0, %1}, %2;" : "=f"(f.x), "=f"(f.y) : "l"(u));
    return f;
}
__device__ __forceinline__ ull f2u(float x, float y) {
    ull u;
    asm("mov.b64 %0, {%1, %2};" : "=l"(u) : "f"(x), "f"(y));
    return u;
}

// ================= dummy launches (shift ncu capture window onto k_input_proj) =================
__global__ void k_nop() {}

// ================= Kernel 1: embedding lookup + input projection GEMM =================
// 128-row x 64-col tiles, 128 threads, thread tile 8x8, f32x2 k-pair packing.
#define XS_STRIDE 102
#define PROJ_SMEM ((128 * XS_STRIDE + 64 * XS_STRIDE) * 4)

__global__ void __launch_bounds__(128) k_input_proj(
    const int* __restrict__ tok, const float* __restrict__ emb,
    const float* __restrict__ wih_f, const float* __restrict__ wih_b,
    const float* __restrict__ bih_f, const float* __restrict__ bhh_f,
    const float* __restrict__ bih_b, const float* __restrict__ bhh_b)
{
    extern __shared__ float psm[];
    float* xs = psm;                    // [128][102]
    float* wc = psm + 128 * XS_STRIDE;  // [64][102]
    const int m0 = blockIdx.x * 128;
    const int c0 = blockIdx.y * 64;
    const int tid = threadIdx.x;

    {
        const int r = tid;
        const int m = m0 + r;
        const int t = m >> 7, b = m & 127;
        const int token = tok[b * TT + t];
        const float4* src = (const float4*)(emb + (size_t)token * DD);
        float* dst = xs + r * XS_STRIDE;
        #pragma unroll
        for (int q = 0; q < 25; ++q) {
            float4 v = src[q];
            *(float2*)(dst + 4 * q)     = make_float2(v.x, v.y);
            *(float2*)(dst + 4 * q + 2) = make_float2(v.z, v.w);
        }
    }
    for (int i = tid; i < 64 * 25; i += 128) {
        const int cc = i / 25, q = i - cc * 25;
        const int col = c0 + cc;
        float4 v = make_float4(0.f, 0.f, 0.f, 0.f);
        if (col < 400)      v = *(const float4*)(wih_f + col * DD + 4 * q);
        else if (col < 800) v = *(const float4*)(wih_b + (col - 400) * DD + 4 * q);
        float* dst = wc + cc * XS_STRIDE + 4 * q;
        *(float2*)(dst)     = make_float2(v.x, v.y);
        *(float2*)(dst + 2) = make_float2(v.z, v.w);
    }
    __syncthreads();

    const int ct = tid >> 4;   // 0..7
    const int rt = tid & 15;   // rows rt + 16*i

    ull acc[8][4][2];
    #pragma unroll
    for (int i = 0; i < 8; ++i)
        #pragma unroll
        for (int j = 0; j < 4; ++j) { acc[i][j][0] = 0ull; acc[i][j][1] = 0ull; }

    #pragma unroll 2
    for (int kp = 0; kp < 50; ++kp) {
        ull xv[8];
        #pragma unroll
        for (int i = 0; i < 8; ++i)
            xv[i] = *(const ull*)(xs + (rt + 16 * i) * XS_STRIDE + 2 * kp);
        ull wv[4][2];
        #pragma unroll
        for (int j = 0; j < 4; ++j) {
            #pragma unroll
            for (int e = 0; e < 2; ++e)
                wv[j][e] = *(const ull*)(wc + (2 * ct + 16 * j + e) * XS_STRIDE + 2 * kp);
        }
        #pragma unroll
        for (int i = 0; i < 8; ++i)
            #pragma unroll
            for (int j = 0; j < 4; ++j) {
                acc[i][j][0] = ffma2(xv[i], wv[j][0], acc[i][j][0]);
                acc[i][j][1] = ffma2(xv[i], wv[j][1], acc[i][j][1]);
            }
    }

    #pragma unroll
    for (int i = 0; i < 8; ++i) {
        const int r = rt + 16 * i;
        const int m = m0 + r;
        const int t = m >> 7, b = m & 127;
        #pragma unroll
        for (int j = 0; j < 4; ++j) {
            const int col = c0 + 2 * ct + 16 * j;
            if (col < 800) {
                float2 s0 = u2f(acc[i][j][0]);
                float2 s1 = u2f(acc[i][j][1]);
                float r0 = s0.x + s0.y;
                float r1 = s1.x + s1.y;
                if (col < 400) {
                    r0 += bih_f[col] + bhh_f[col];
                    r1 += bih_f[col + 1] + bhh_f[col + 1];
                    *(float2*)(&g_gin[0][t][b][col]) = make_float2(r0, r1);
                } else {
                    const int c2 = col - 400;
                    r0 += bih_b[c2] + bhh_b[c2];
                    r1 += bih_b[c2 + 1] + bhh_b[c2 + 1];
                    *(float2*)(&g_gin[1][t][b][c2]) = make_float2(r0, r1);
                }
            }
        }
    }
}

// ================= Kernel 2: LSTM recurrence — split-K, 800 threads =================
// thread = (g = tid>>1, ks = tid&1). ks0 owns K[0..51] (pairs 24,25 zeroed ->
// effectively K[0..47]), ks1 owns K[48..99]. Each thread accumulates partials
// for BOTH batch elems over its K-half; one shfl_xor(1) per elem combines the
// halves; lane ks then owns elem ks's full pre-activation + activation.
__global__ void __launch_bounds__(800, 1) k_lstm(
    const float* __restrict__ whh_f, const float* __restrict__ whh_b)
{
    __shared__ __align__(16) float hsm[208];  // [elem][104] padded
    __shared__ float gbuf[800];               // [elem][gate]

    const int dir = blockIdx.y;
    const int b0  = blockIdx.x * 2;
    const int tid = threadIdx.x;
    const int g   = tid >> 1;                 // gate 0..399
    const int ks  = tid & 1;                  // K-half
    const int kbase = 48 * ks;
    const float* wrow = (dir ? whh_b : whh_f) + g * 100 + kbase;

    // 26 packed weight pairs for this K-half; ks0 zeroes overlap pairs 24,25
    ull w[26];
    #pragma unroll
    for (int q = 0; q < 26; ++q) {
        float lo = wrow[2 * q], hi = wrow[2 * q + 1];
        if (ks == 0 && q >= 24) { lo = 0.f; hi = 0.f; }
        w[q] = f2u(lo, hi);
    }

    if (tid < 208) hsm[tid] = 0.f;
    float cv = 0.f;
    __syncthreads();

    const int gtype = g / 100;
    int t = dir ? (TT - 1) : 0;
    const int tstep = dir ? -1 : 1;
    // lane ks loads gin for elem ks only
    float pre = g_gin[dir][t][b0 + ks][g];
    const unsigned FULL = 0xffffffffu;

    const float* hb0 = hsm + kbase;           // elem 0, this K-half
    const float* hb1 = hsm + 104 + kbase;     // elem 1

    const int pe = (tid >= 100 && tid < 200) ? 1 : 0;   // pointwise owner mapping
    const int pk = tid - 100 * pe;

    for (int s = 0; s < TT; ++s, t += tstep) {
        int tn = t + tstep;
        tn = (tn < 0) ? 0 : ((tn > TT - 1) ? TT - 1 : tn);
        float nx = g_gin[dir][tn][b0 + ks][g];

        ull a0a = 0ull, a0b = 0ull, a1a = 0ull, a1b = 0ull;
        #pragma unroll
        for (int q4 = 0; q4 < 13; ++q4) {
            ulonglong2 h0 = *(const ulonglong2*)(hb0 + 4 * q4);
            ulonglong2 h1 = *(const ulonglong2*)(hb1 + 4 * q4);
            a0a = ffma2(w[2 * q4],     h0.x, a0a);
            a0b = ffma2(w[2 * q4 + 1], h0.y, a0b);
            a1a = ffma2(w[2 * q4],     h1.x, a1a);
            a1b = ffma2(w[2 * q4 + 1], h1.y, a1b);
        }
        float2 s0a = u2f(a0a), s0b = u2f(a0b), s1a = u2f(a1a), s1b = u2f(a1b);
        float p0 = (s0a.x + s0a.y) + (s0b.x + s0b.y);   // elem0 partial, my K-half
        float p1 = (s1a.x + s1a.y) + (s1b.x + s1b.y);   // elem1 partial
        float q0 = __shfl_xor_sync(FULL, p0, 1);
        float q1 = __shfl_xor_sync(FULL, p1, 1);
        // lane ks owns elem ks's full sum (fixed order: ks0-half + ks1-half)
        float half0 = ks ? q0 : p0;   // elem-my K[0..47] partial
        float half1 = ks ? p1 : q1;   // elem-my K[48..99] partial
        float full_sum = ks ? (half1 + q1 - q1 + half0) : 0.f;  // placeholder avoided below
        // (compute cleanly:)
        float mysum = (ks ? q0 : p0);          // low-half partial of MY elem? no:
        // For elem = ks: low half (K0..47) partial lives in lane ks0, high half in ks1.
        // p0/p1 are indexed by ELEM, not half. My elem's partial on my half:
        float mine_half  = ks ? p1 : p0;       // (elem=ks, half=ks)
        float other_half = ks ? q1 : q0;       // (elem=ks, half=1-ks)
        float lowh  = ks ? other_half : mine_half;
        float highh = ks ? mine_half  : other_half;
        float acc = pre + (lowh + highh);
        (void)full_sum; (void)mysum; (void)half0; (void)half1;

        float v = (gtype == 2) ? htanh(acc) : hsig(acc);
        gbuf[ks * 400 + g] = v;
        __syncthreads();

        if (tid < 200) {
            const int base = 400 * pe;
            float iv = gbuf[base + pk],       fv = gbuf[base + pk + 100];
            float gv = gbuf[base + pk + 200], ov = gbuf[base + pk + 300];
            cv = fv * cv + iv * gv;
            float hv = ov * htanh(cv);
            hsm[104 * pe + pk] = hv;
            g_h[dir][t][b0 + pe][pk] = hv;
        }
        pre = nx;
        __syncthreads();
    }
}

// ================= Kernel 3: emissions — 64-row tiles for 3 blocks/SM =================
#define HS_STRIDE 202
#define EMIT_SMEM ((64 * HS_STRIDE + 25 * HS_STRIDE) * 4)

__global__ void __launch_bounds__(320) k_emit(
    const float* __restrict__ wtag, const float* __restrict__ btag)
{
    extern __shared__ float esm[];
    float* hs = esm;                   // [64][202]
    float* wt = esm + 64 * HS_STRIDE;  // [25][202]
    const int tid = threadIdx.x;
    const int m0 = blockIdx.x * 64;

    for (int i = tid; i < 25 * 100; i += 320) {
        const int l = i / 100, kp = i - l * 100;
        *(float2*)(wt + l * HS_STRIDE + 2 * kp) = *(const float2*)(wtag + l * 200 + 2 * kp);
    }
    for (int i = tid; i < 64 * 100; i += 320) {
        const int r = i / 100, kp = i - r * 100;
        const int m = m0 + r;
        const int t = m >> 7, b = m & 127;
        const int kk = 2 * kp;
        float2 v = (kk < 100) ? *(const float2*)(&g_h[0][t][b][kk])
                              : *(const float2*)(&g_h[1][t][b][kk - 100]);
        *(float2*)(hs + r * HS_STRIDE + kk) = v;
    }
    __syncthreads();

    const int r  = tid / 5;
    const int lg = tid - r * 5;
    ull acc[5];
    #pragma unroll
    for (int j = 0; j < 5; ++j) acc[j] = 0ull;

    const float* hp = hs + r * HS_STRIDE;
    #pragma unroll 4
    for (int kp = 0; kp < 100; ++kp) {
        ull hv = *(const ull*)(hp + 2 * kp);
        #pragma unroll
        for (int j = 0; j < 5; ++j) {
            ull wv = *(const ull*)(wt + (5 * lg + j) * HS_STRIDE + 2 * kp);
            acc[j] = ffma2(hv, wv, acc[j]);
        }
    }
    {
        const int m = m0 + r;
        const int t = m >> 7, b = m & 127;
        #pragma unroll
        for (int j = 0; j < 5; ++j) {
            const int l = 5 * lg + j;
            float2 p = u2f(acc[j]);
            g_em[((size_t)b * TT + t) * LL + l] = p.x + p.y + btag[l];
        }
    }
}

// ================= Kernel 4: CRF NLL (scaled-prob forward, depth-7 chains) =================
__global__ void __launch_bounds__(32) k_crf(
    const float* __restrict__ trans, const float* __restrict__ strans,
    const float* __restrict__ etrans, const int* __restrict__ tags,
    const int* __restrict__ lengths)
{
    __shared__ float E[640];
    __shared__ float tr[640];
    __shared__ float As[32];
    const int b = blockIdx.x;
    const int lane = threadIdx.x;

    for (int i = lane; i < 625; i += 32) {
        float v = trans[i];
        tr[i] = v;
        E[i] = __expf(v);
    }
    __syncwarp();

    const int len = lengths[b];
    const int* tg = tags + b * TT;
    const float* em = g_em + (size_t)b * TT * LL;

    float gp = 0.f;
    for (int t = 1 + lane; t < TT; t += 32) {
        if (t < len) {
            int tp = tg[t - 1], tc = tg[t];
            gp += tr[tp * 25 + tc] + em[t * LL + tc];
        }
    }
    #pragma unroll
    for (int off = 16; off; off >>= 1) gp += __shfl_down_sync(0xffffffffu, gp, off);
    float gold = __shfl_sync(0xffffffffu, gp, 0);
    if (lane == 0) {
        int t0 = tg[0];
        gold += strans[t0] + em[t0];
        gold += etrans[tg[len - 1]];
    }
    gold = __shfl_sync(0xffffffffu, gold, 0);

    float A = 0.f, off = 0.f;
    if (lane < LL) A = __expf(strans[lane] + em[lane]);
    As[lane] = A;
    __syncwarp();

    float emn = (lane < LL) ? em[LL + lane] : 0.f;
    for (int t = 1; t < TT; ++t) {
        const float emc = emn;
        const int t2 = (t + 1 < TT) ? (t + 1) : t;
        emn = (lane < LL) ? em[t2 * LL + lane] : 0.f;

        if (t < len) {
            float s0 = 0.f, s1 = 0.f, s2 = 0.f, s3 = 0.f;
            #pragma unroll
            for (int p = 0; p < 24; p += 4) {
                s0 = fmaf(As[p],     E[p * 25 + lane],       s0);
                s1 = fmaf(As[p + 1], E[(p + 1) * 25 + lane], s1);
                s2 = fmaf(As[p + 2], E[(p + 2) * 25 + lane], s2);
                s3 = fmaf(As[p + 3], E[(p + 3) * 25 + lane], s3);
            }
            s0 = fmaf(As[24], E[24 * 25 + lane], s0);
            A = ((s0 + s1) + (s2 + s3)) * __expf(emc);
        }
        if ((t & 15) == 15) {
            float m = A;
            #pragma unroll
            for (int o = 16; o; o >>= 1) m = fmaxf(m, __shfl_xor_sync(0xffffffffu, m, o));
            off += __logf(m);
            A = __fdividef(A, m);
        }
        __syncwarp();
        As[lane] = A;
        __syncwarp();
    }

    float val = (lane < LL) ? A * __expf(etrans[lane]) : 0.f;
    #pragma unroll
    for (int o = 16; o; o >>= 1) val += __shfl_xor_sync(0xffffffffu, val, o);
    float logZ = off + __logf(val);
    if (lane == 0) g_res[b] = logZ - gold;
}

// ================= Kernel 5: final fixed-order reduction =================
__global__ void __launch_bounds__(128) k_reduce(float* __restrict__ out)
{
    __shared__ float s[128];
    s[threadIdx.x] = g_res[threadIdx.x];
    __syncthreads();
    for (int st = 64; st > 0; st >>= 1) {
        if (threadIdx.x < st) s[threadIdx.x] += s[threadIdx.x + st];
        __syncthreads();
    }
    if (threadIdx.x == 0) out[0] = s[0];
}

// ================= launch =================
extern "C" void kernel_launch(void* const* d_in, const int* in_sizes, int n_in,
                              void* d_out, int out_size)
{
    const int*   tok     = (const int*)  d_in[0];
    const int*   tag     = (const int*)  d_in[1];
    const int*   lengths = (const int*)  d_in[2];
    const float* emb     = (const float*)d_in[3];
    const float* wih_f   = (const float*)d_in[4];
    const float* whh_f   = (const float*)d_in[5];
    const float* bih_f   = (const float*)d_in[6];
    const float* bhh_f   = (const float*)d_in[7];
    const float* wih_b   = (const float*)d_in[8];
    const float* whh_b   = (const float*)d_in[9];
    const float* bih_b   = (const float*)d_in[10];
    const float* bhh_b   = (const float*)d_in[11];
    const float* wtag    = (const float*)d_in[12];
    const float* btag    = (const float*)d_in[13];
    const float* trans   = (const float*)d_in[14];
    const float* strans  = (const float*)d_in[15];
    const float* etrans  = (const float*)d_in[16];
    float* out = (float*)d_out;

    cudaFuncSetAttribute(k_input_proj, cudaFuncAttributeMaxDynamicSharedMemorySize, PROJ_SMEM);
    cudaFuncSetAttribute(k_emit, cudaFuncAttributeMaxDynamicSharedMemorySize, EMIT_SMEM);

    // three no-op launches shift the ncu capture window (4th launch) onto k_input_proj
    k_nop<<<1, 32>>>();
    k_nop<<<1, 32>>>();
    k_nop<<<1, 32>>>();
    k_input_proj<<<dim3(512, 13), 128, PROJ_SMEM>>>(tok, emb, wih_f, wih_b,
                                                    bih_f, bhh_f, bih_b, bhh_b);
    k_lstm<<<dim3(64, 2), 800>>>(whh_f, whh_b);
    k_emit<<<1024, 320, EMIT_SMEM>>>(wtag, btag);
    k_crf<<<128, 32>>>(trans, strans, etrans, tag, lengths);
    k_reduce<<<1, 128>>>(out);
}